// round 2
// baseline (speedup 1.0000x reference)
#include <cuda_runtime.h>
#include <cuda_bf16.h>
#include <cstdint>

// ============================ constants ============================
#define NR        200               // number of masks
#define HW        200704            // 448*448
#define NTK       3136              // total K tiles of 64 (200704/64)
#define GRID      148
#define NTHREADS  512
#define ROWSTR    144               // bytes per row in bf16 mma buffer (72 bf16, padded)
#define STAGE_BYTES (200*64*4)      // 51200 fp32 staging
#define BUF_OFF   STAGE_BYTES
#define BUF_BYTES (224*ROWSTR)      // 32256
#define SMEM_TOTAL (STAGE_BYTES + BUF_BYTES)   // 83456
#define NTOUT     28                // upper-tri 32x32 output tiles (7x7 grid)

__device__ float g_scratch[(size_t)GRID * NTOUT * 1024];   // ~17 MB
__device__ float g_inter[NR * NR];

// upper-tri tile coords (ti <= tj), 7x7 grid
__device__ __constant__ unsigned char TIa[NTOUT] =
    {0,0,0,0,0,0,0, 1,1,1,1,1,1, 2,2,2,2,2, 3,3,3,3, 4,4,4, 5,5, 6};
__device__ __constant__ unsigned char TJa[NTOUT] =
    {0,1,2,3,4,5,6, 1,2,3,4,5,6, 2,3,4,5,6, 3,4,5,6, 4,5,6, 5,6, 6};

// ============================ PTX helpers (non-'a' ISA only) ============================
__device__ __forceinline__ uint32_t smem_u32(const void* p) {
    uint32_t a;
    asm("{ .reg .u64 t; cvta.to.shared.u64 t, %1; cvt.u32.u64 %0, t; }"
        : "=r"(a) : "l"(p));
    return a;
}

__device__ __forceinline__ void cp_async16(uint32_t sdst, const void* gsrc) {
    asm volatile("cp.async.cg.shared.global [%0], [%1], 16;"
                 :: "r"(sdst), "l"(gsrc) : "memory");
}
#define CP_COMMIT() asm volatile("cp.async.commit_group;" ::: "memory")
#define CP_WAIT0()  asm volatile("cp.async.wait_group 0;" ::: "memory")

__device__ __forceinline__ void ldsm4(uint32_t* r, uint32_t addr) {
    asm volatile("ldmatrix.sync.aligned.m8n8.x4.shared.b16 {%0,%1,%2,%3}, [%4];"
                 : "=r"(r[0]), "=r"(r[1]), "=r"(r[2]), "=r"(r[3]) : "r"(addr));
}

__device__ __forceinline__ void mma16816(float* d, const uint32_t* a, const uint32_t* b) {
    asm volatile(
        "mma.sync.aligned.m16n8k16.row.col.f32.bf16.bf16.f32 "
        "{%0,%1,%2,%3}, {%4,%5,%6,%7}, {%8,%9}, {%0,%1,%2,%3};"
        : "+f"(d[0]), "+f"(d[1]), "+f"(d[2]), "+f"(d[3])
        : "r"(a[0]), "r"(a[1]), "r"(a[2]), "r"(a[3]), "r"(b[0]), "r"(b[1]));
}

// ============================ kernel 1: split-K Gram via mma.sync ============================
// CTA b owns K tiles [b*NTK/GRID, (b+1)*NTK/GRID). Per tile: cp.async fp32 ->
// stage, cvt -> bf16 buf (rows 200..223 zero). One buf feeds both MMA operands
// (Gram). 16 warps cover the 28 upper-tri 32x32 output tiles (warp w: tiles
// w and w+16). fp32 partials go to g_scratch[b].
__global__ __launch_bounds__(NTHREADS, 1)
void gram_kernel(const float* __restrict__ seg) {
    extern __shared__ char smem[];
    const uint32_t sbase = smem_u32(smem);
    const uint32_t stage = sbase;
    const uint32_t buf   = sbase + BUF_OFF;
    const int tid = threadIdx.x;
    const int wid = tid >> 5;
    const int lid = tid & 31;
    const int bid = blockIdx.x;

    const int t0 = (bid * NTK) / GRID;
    const int t1 = ((bid + 1) * NTK) / GRID;

    // zero pad rows 200..223 (contiguous region, written once, never touched again)
    for (int i = tid; i < (24 * ROWSTR) / 4; i += NTHREADS)
        *reinterpret_cast<uint32_t*>(smem + BUF_OFF + 200 * ROWSTR + i * 4) = 0u;

    // this warp's output tiles
    const int tl0 = wid;
    const int tl1 = wid + 16;
    const int nt = (tl1 < NTOUT) ? 2 : 1;
    int tis[2], tjs[2];
    tis[0] = TIa[tl0]; tjs[0] = TJa[tl0];
    tis[1] = TIa[(tl1 < NTOUT) ? tl1 : 0];
    tjs[1] = TJa[(tl1 < NTOUT) ? tl1 : 0];

    float acc[2][2][4][4];   // [tile][m-half][n-quarter][regs]
    #pragma unroll
    for (int a = 0; a < 2; a++)
        #pragma unroll
        for (int b = 0; b < 2; b++)
            #pragma unroll
            for (int c = 0; c < 4; c++)
                #pragma unroll
                for (int d = 0; d < 4; d++) acc[a][b][c][d] = 0.f;

    // ldmatrix lane address offsets (A: m16k16 x4; B: two n8k16 via x4)
    const uint32_t aoff = (uint32_t)(lid & 15) * ROWSTR + (uint32_t)((lid >> 4) << 4);
    const uint32_t boff = (uint32_t)(((lid >> 4) << 3) + (lid & 7)) * ROWSTR
                        + (uint32_t)(((lid >> 3) & 1) << 4);

    // ---- prologue: stage tile t0 ----
    for (int idx = tid; idx < 3200; idx += NTHREADS) {
        int row = idx >> 4, c4 = idx & 15;
        cp_async16(stage + (uint32_t)idx * 16,
                   seg + (size_t)row * HW + (size_t)t0 * 64 + c4 * 4);
    }
    CP_COMMIT();
    CP_WAIT0();
    __syncthreads();
    // cvt stage -> bf16 buf
    for (int idx = tid; idx < 3200; idx += NTHREADS) {
        int row = idx >> 4, c4 = idx & 15;
        float4 v = *reinterpret_cast<const float4*>(smem + (size_t)idx * 16);
        __nv_bfloat162 p0 = __floats2bfloat162_rn(v.x, v.y);
        __nv_bfloat162 p1 = __floats2bfloat162_rn(v.z, v.w);
        uint2 w;
        w.x = *reinterpret_cast<uint32_t*>(&p0);
        w.y = *reinterpret_cast<uint32_t*>(&p1);
        *reinterpret_cast<uint2*>(smem + BUF_OFF + (size_t)row * ROWSTR + c4 * 8) = w;
    }
    __syncthreads();

    // ---- main loop ----
    for (int t = t0; t < t1; t++) {
        const bool more = (t + 1 < t1);
        if (more) {
            for (int idx = tid; idx < 3200; idx += NTHREADS) {
                int row = idx >> 4, c4 = idx & 15;
                cp_async16(stage + (uint32_t)idx * 16,
                           seg + (size_t)row * HW + (size_t)(t + 1) * 64 + c4 * 4);
            }
            CP_COMMIT();
        }

        // compute 4 K-steps from bf16 buf
        #pragma unroll
        for (int ks = 0; ks < 4; ks++) {
            const uint32_t koff = (uint32_t)ks * 32;   // 16 bf16 = 32 bytes
            #pragma unroll
            for (int tt = 0; tt < 2; tt++) {
                if (tt < nt) {
                    uint32_t afr[2][4], bfr[2][4];
                    uint32_t aA = buf + (uint32_t)(tis[tt] * 32) * ROWSTR + aoff + koff;
                    uint32_t aB = buf + (uint32_t)(tjs[tt] * 32) * ROWSTR + boff + koff;
                    ldsm4(afr[0], aA);
                    ldsm4(afr[1], aA + 16 * ROWSTR);
                    ldsm4(bfr[0], aB);
                    ldsm4(bfr[1], aB + 16 * ROWSTR);
                    #pragma unroll
                    for (int mh = 0; mh < 2; mh++)
                        #pragma unroll
                        for (int nq = 0; nq < 4; nq++)
                            mma16816(acc[tt][mh][nq], afr[mh], &bfr[nq >> 1][(nq & 1) * 2]);
                }
            }
        }

        if (more) {
            CP_WAIT0();
            __syncthreads();     // all warps done reading buf; staged data visible
            for (int idx = tid; idx < 3200; idx += NTHREADS) {
                int row = idx >> 4, c4 = idx & 15;
                float4 v = *reinterpret_cast<const float4*>(smem + (size_t)idx * 16);
                __nv_bfloat162 p0 = __floats2bfloat162_rn(v.x, v.y);
                __nv_bfloat162 p1 = __floats2bfloat162_rn(v.z, v.w);
                uint2 w;
                w.x = *reinterpret_cast<uint32_t*>(&p0);
                w.y = *reinterpret_cast<uint32_t*>(&p1);
                *reinterpret_cast<uint2*>(smem + BUF_OFF + (size_t)row * ROWSTR + c4 * 8) = w;
            }
            __syncthreads();
        }
    }

    // ---- epilogue: fp32 partials -> scratch ----
    #pragma unroll
    for (int tt = 0; tt < 2; tt++) {
        if (tt < nt) {
            const int tl = (tt == 0) ? tl0 : tl1;
            float* dst = g_scratch + (size_t)bid * (NTOUT * 1024) + (size_t)tl * 1024;
            #pragma unroll
            for (int mh = 0; mh < 2; mh++) {
                #pragma unroll
                for (int nq = 0; nq < 4; nq++) {
                    const int r = mh * 16 + (lid >> 2);
                    const int c = nq * 8 + (lid & 3) * 2;
                    float2 lo = make_float2(acc[tt][mh][nq][0], acc[tt][mh][nq][1]);
                    float2 hi = make_float2(acc[tt][mh][nq][2], acc[tt][mh][nq][3]);
                    *reinterpret_cast<float2*>(dst + (size_t)r * 32 + c) = lo;
                    *reinterpret_cast<float2*>(dst + (size_t)(r + 8) * 32 + c) = hi;
                }
            }
        }
    }
}

// ============================ kernel 2: reduce split-K partials ============================
__global__ void reduce_kernel() {
    const int idx = blockIdx.x * 256 + threadIdx.x;   // < 28672
    const float* p = g_scratch + idx;
    float a0 = 0.f, a1 = 0.f, a2 = 0.f, a3 = 0.f;
    #pragma unroll 4
    for (int s = 0; s < GRID; s += 4) {
        a0 += p[(size_t)(s + 0) * (NTOUT * 1024)];
        a1 += p[(size_t)(s + 1) * (NTOUT * 1024)];
        a2 += p[(size_t)(s + 2) * (NTOUT * 1024)];
        a3 += p[(size_t)(s + 3) * (NTOUT * 1024)];
    }
    const float sum = (a0 + a1) + (a2 + a3);
    const int tl = idx >> 10;
    const int r = (idx >> 5) & 31;
    const int c = idx & 31;
    const int gi = TIa[tl] * 32 + r;
    const int gj = TJa[tl] * 32 + c;
    if (gi < NR && gj < NR) g_inter[gi * NR + gj] = sum;
}

// ============================ kernel 3: matrix NMS math (exact jnp semantics) ============================
__global__ void final_kernel(const float* __restrict__ scores,
                             const int* __restrict__ labels,
                             float* __restrict__ out) {
    extern __shared__ float sI[];       // 200x200 inter (upper tri + diag valid)
    __shared__ float sums[NR];
    __shared__ float comp[NR];
    __shared__ int   lab[NR];
    __shared__ float sc[NR];
    const int tid = threadIdx.x;

    for (int idx = tid; idx < NR * NR; idx += 256) sI[idx] = g_inter[idx];
    if (tid < NR) { lab[tid] = labels[tid]; sc[tid] = scores[tid]; }
    __syncthreads();
    if (tid < NR) sums[tid] = sI[tid * NR + tid];   // diag = mask area (binary masks)
    __syncthreads();

    // compensate_iou[j] = max_{i<j, same label} iou(i,j)
    if (tid < NR) {
        const int j = tid;
        const int lj = lab[j];
        const float sj = sums[j];
        float m = 0.f;
        for (int i = 0; i < j; i++) {
            if (lab[i] == lj) {
                float in_ = sI[i * NR + j];
                m = fmaxf(m, in_ / (sums[i] + sj - in_));
            }
        }
        comp[j] = m;
    }
    __syncthreads();

    // decay_coef[j] = exp(sigma * min_i (comp[i]^2 - d_ij^2)), min over ALL i
    if (tid < NR) {
        const int j = tid;
        const int lj = lab[j];
        const float sj = sums[j];
        float mn = 3.4e38f;
        for (int i = 0; i < NR; i++) {
            float d = 0.f;
            if (i < j && lab[i] == lj) {
                float in_ = sI[i * NR + j];
                d = in_ / (sums[i] + sj - in_);
            }
            float c = comp[i];
            mn = fminf(mn, c * c - d * d);
        }
        out[j] = sc[j] * expf(2.0f * mn);   // SIGMA = 2
    }
}

// ============================ launch ============================
extern "C" void kernel_launch(void* const* d_in, const int* in_sizes, int n_in,
                              void* d_out, int out_size) {
    const float* seg    = (const float*)d_in[0];
    const float* scores = (const float*)d_in[1];
    const int*   labels = (const int*)d_in[2];
    float* out = (float*)d_out;

    cudaFuncSetAttribute(gram_kernel, cudaFuncAttributeMaxDynamicSharedMemorySize, SMEM_TOTAL);
    cudaFuncSetAttribute(final_kernel, cudaFuncAttributeMaxDynamicSharedMemorySize,
                         NR * NR * (int)sizeof(float));

    gram_kernel<<<GRID, NTHREADS, SMEM_TOTAL>>>(seg);
    reduce_kernel<<<112, 256>>>();
    final_kernel<<<1, 256, NR * NR * sizeof(float)>>>(scores, labels, out);
}

// round 3
// speedup vs baseline: 1.0070x; 1.0070x over previous
#include <cuda_runtime.h>
#include <cstdint>

// ============================ constants ============================
#define NR        200               // number of masks
#define HW        200704            // 448*448
#define NTK       3136              // total K tiles of 64 (200704/64)
#define GRID      148
#define NTHREADS  512
#define RS        80                // fp8 buffer row stride (64 data + 16 pad)
#define STAGE_B   51200             // 200 rows * 64 fp32
#define BUF_B     (224*RS)          // 17920
#define OFF_STAGE0 0
#define OFF_STAGE1 STAGE_B
#define OFF_BUF0  (2*STAGE_B)
#define OFF_BUF1  (2*STAGE_B + BUF_B)
#define PIPE_SMEM (2*STAGE_B + 2*BUF_B)     // 138240
#define DYN_SMEM  163840                    // max(pipeline, 200*200*4 for final)
#define NTOUT     28                // upper-tri 32x32 output tiles (7x7 grid)

__device__ float g_scratch[(size_t)GRID * NTOUT * 1024];   // ~17 MB
__device__ float g_inter[NR * NR];
__device__ unsigned g_count;     // zero-initialized; barrier resets it each use
__device__ unsigned g_gen;       // monotonically increasing across replays (safe)

__device__ __constant__ unsigned char TIa[NTOUT] =
    {0,0,0,0,0,0,0, 1,1,1,1,1,1, 2,2,2,2,2, 3,3,3,3, 4,4,4, 5,5, 6};
__device__ __constant__ unsigned char TJa[NTOUT] =
    {0,1,2,3,4,5,6, 1,2,3,4,5,6, 2,3,4,5,6, 3,4,5,6, 4,5,6, 5,6, 6};

// ============================ helpers ============================
__device__ __forceinline__ uint32_t smem_u32(const void* p) {
    uint32_t a;
    asm("{ .reg .u64 t; cvta.to.shared.u64 t, %1; cvt.u32.u64 %0, t; }"
        : "=r"(a) : "l"(p));
    return a;
}

__device__ __forceinline__ void cp_async16(uint32_t sdst, const void* gsrc) {
    asm volatile("cp.async.cg.shared.global [%0], [%1], 16;"
                 :: "r"(sdst), "l"(gsrc) : "memory");
}
#define CP_COMMIT() asm volatile("cp.async.commit_group;" ::: "memory")
#define CP_WAIT(n)  asm volatile("cp.async.wait_group %0;" :: "n"(n) : "memory")

__device__ __forceinline__ void ldsm4(uint32_t* r, uint32_t addr) {
    asm volatile("ldmatrix.sync.aligned.m8n8.x4.shared.b16 {%0,%1,%2,%3}, [%4];"
                 : "=r"(r[0]), "=r"(r[1]), "=r"(r[2]), "=r"(r[3]) : "r"(addr));
}

// fp8 e4m3 MMA, K=32 per instruction (base ISA, sm_89+)
__device__ __forceinline__ void mma16832(float* d, const uint32_t* a, const uint32_t* b) {
    asm volatile(
        "mma.sync.aligned.m16n8k32.row.col.f32.e4m3.e4m3.f32 "
        "{%0,%1,%2,%3}, {%4,%5,%6,%7}, {%8,%9}, {%0,%1,%2,%3};"
        : "+f"(d[0]), "+f"(d[1]), "+f"(d[2]), "+f"(d[3])
        : "r"(a[0]), "r"(a[1]), "r"(a[2]), "r"(a[3]), "r"(b[0]), "r"(b[1]));
}

// sense-reversal grid barrier; requires all GRID CTAs co-resident (1 CTA/SM)
__device__ __forceinline__ void grid_barrier() {
    __syncthreads();
    if (threadIdx.x == 0) {
        __threadfence();                                  // release my writes
        unsigned gen = atomicAdd(&g_gen, 0u);             // snapshot BEFORE arriving
        unsigned arrived = atomicAdd(&g_count, 1u) + 1u;
        if (arrived == GRID) {
            atomicExch(&g_count, 0u);                     // reset for next use
            __threadfence();
            atomicAdd(&g_gen, 1u);                        // release all
        } else {
            while (atomicAdd(&g_gen, 0u) == gen) { }
        }
        __threadfence();                                  // acquire remote writes
    }
    __syncthreads();
}

// stage fp32 tile t (200 rows x 64 cols) via cp.async
__device__ __forceinline__ void issue_stage(uint32_t stage, const float* seg, int t, int tid) {
    #pragma unroll
    for (int it = 0; it < 7; it++) {
        int idx = tid + it * NTHREADS;
        if (idx < 3200) {
            int row = idx >> 4, c4 = idx & 15;
            cp_async16(stage + (uint32_t)idx * 16,
                       seg + (size_t)row * HW + (size_t)t * 64 + c4 * 4);
        }
    }
    CP_COMMIT();
}

// convert staged fp32 -> fp8 buffer (rows 200..223 pre-zeroed)
__device__ __forceinline__ void convert_stage(char* smem, int stage_off, int buf_off, int tid) {
    #pragma unroll
    for (int it = 0; it < 7; it++) {
        int idx = tid + it * NTHREADS;
        if (idx < 3200) {
            int row = idx >> 4, c4 = idx & 15;
            float4 v = *reinterpret_cast<const float4*>(smem + stage_off + (size_t)idx * 16);
            uint16_t p0, p1;
            asm("cvt.rn.satfinite.e4m3x2.f32 %0, %1, %2;" : "=h"(p0) : "f"(v.y), "f"(v.x));
            asm("cvt.rn.satfinite.e4m3x2.f32 %0, %1, %2;" : "=h"(p1) : "f"(v.w), "f"(v.z));
            uint32_t w = (uint32_t)p0 | ((uint32_t)p1 << 16);
            *reinterpret_cast<uint32_t*>(smem + buf_off + (size_t)row * RS + c4 * 4) = w;
        }
    }
}

// ============================ fused kernel ============================
__global__ __launch_bounds__(NTHREADS, 1)
void fused_kernel(const float* __restrict__ seg,
                  const float* __restrict__ scores,
                  const int* __restrict__ labels,
                  float* __restrict__ out) {
    extern __shared__ char smem[];
    const uint32_t sbase = smem_u32(smem);
    const int tid = threadIdx.x;
    const int wid = tid >> 5;
    const int lid = tid & 31;
    const int bid = blockIdx.x;

    // ================= phase 1: split-K Gram (fp8 mma) =================
    {
        const int t0 = (bid * NTK) / GRID;
        const int t1 = ((bid + 1) * NTK) / GRID;

        // zero pad rows 200..223 of both fp8 buffers (written once)
        for (int i = tid; i < (24 * RS) / 4; i += NTHREADS) {
            *reinterpret_cast<uint32_t*>(smem + OFF_BUF0 + 200 * RS + i * 4) = 0u;
            *reinterpret_cast<uint32_t*>(smem + OFF_BUF1 + 200 * RS + i * 4) = 0u;
        }

        const int tl0 = wid;
        const int tl1 = wid + 16;
        const int nt = (tl1 < NTOUT) ? 2 : 1;
        int tis[2], tjs[2];
        tis[0] = TIa[tl0]; tjs[0] = TJa[tl0];
        tis[1] = TIa[(tl1 < NTOUT) ? tl1 : 0];
        tjs[1] = TJa[(tl1 < NTOUT) ? tl1 : 0];

        float acc[2][2][4][4];
        #pragma unroll
        for (int a = 0; a < 2; a++)
            #pragma unroll
            for (int b = 0; b < 2; b++)
                #pragma unroll
                for (int c = 0; c < 4; c++)
                    #pragma unroll
                    for (int d = 0; d < 4; d++) acc[a][b][c][d] = 0.f;

        // ldmatrix lane offsets (fp8: same byte layout as bf16 reinterpreted, K=32/ldsm)
        const uint32_t aoff = (uint32_t)(lid & 15) * RS + (uint32_t)((lid >> 4) << 4);
        const uint32_t boff = (uint32_t)(((lid >> 4) << 3) + (lid & 7)) * RS
                            + (uint32_t)(((lid >> 3) & 1) << 4);

        // prologue: issue t0 (+t0+1), wait t0, convert into buf0
        issue_stage(sbase + OFF_STAGE0 + ((t0 & 1) ? STAGE_B - STAGE_B : 0) + (uint32_t)((t0 & 1) * STAGE_B), seg, t0, tid);
        if (t0 + 1 < t1) {
            issue_stage(sbase + (uint32_t)(((t0 + 1) & 1) * STAGE_B), seg, t0 + 1, tid);
            CP_WAIT(1);
        } else {
            CP_WAIT(0);
        }
        convert_stage(smem, (t0 & 1) * STAGE_B, OFF_BUF0 + (t0 & 1) * BUF_B, tid);
        __syncthreads();

        for (int t = t0; t < t1; t++) {
            if (t + 2 < t1)
                issue_stage(sbase + (uint32_t)(((t + 2) & 1) * STAGE_B), seg, t + 2, tid);

            // compute tile t from buf[t&1] : 2 K-steps of K=32
            const uint32_t buf = sbase + OFF_BUF0 + (uint32_t)((t & 1) * BUF_B);
            #pragma unroll
            for (int ks = 0; ks < 2; ks++) {
                const uint32_t koff = (uint32_t)ks * 32;
                #pragma unroll
                for (int tt = 0; tt < 2; tt++) {
                    if (tt < nt) {
                        uint32_t afr[2][4], bfr[2][4];
                        uint32_t aA = buf + (uint32_t)(tis[tt] * 32) * RS + aoff + koff;
                        uint32_t aB = buf + (uint32_t)(tjs[tt] * 32) * RS + boff + koff;
                        ldsm4(afr[0], aA);
                        ldsm4(afr[1], aA + 16 * RS);
                        ldsm4(bfr[0], aB);
                        ldsm4(bfr[1], aB + 16 * RS);
                        #pragma unroll
                        for (int mh = 0; mh < 2; mh++)
                            #pragma unroll
                            for (int nq = 0; nq < 4; nq++)
                                mma16832(acc[tt][mh][nq], afr[mh], &bfr[nq >> 1][(nq & 1) * 2]);
                    }
                }
            }

            if (t + 1 < t1) {
                if (t + 2 < t1) { CP_WAIT(1); } else { CP_WAIT(0); }
                convert_stage(smem, ((t + 1) & 1) * STAGE_B,
                              OFF_BUF0 + ((t + 1) & 1) * BUF_B, tid);
                __syncthreads();
            }
        }

        // epilogue: fp32 partials -> scratch
        #pragma unroll
        for (int tt = 0; tt < 2; tt++) {
            if (tt < nt) {
                const int tl = (tt == 0) ? tl0 : tl1;
                float* dst = g_scratch + (size_t)bid * (NTOUT * 1024) + (size_t)tl * 1024;
                #pragma unroll
                for (int mh = 0; mh < 2; mh++) {
                    #pragma unroll
                    for (int nq = 0; nq < 4; nq++) {
                        const int r = mh * 16 + (lid >> 2);
                        const int c = nq * 8 + (lid & 3) * 2;
                        *reinterpret_cast<float2*>(dst + (size_t)r * 32 + c) =
                            make_float2(acc[tt][mh][nq][0], acc[tt][mh][nq][1]);
                        *reinterpret_cast<float2*>(dst + (size_t)(r + 8) * 32 + c) =
                            make_float2(acc[tt][mh][nq][2], acc[tt][mh][nq][3]);
                    }
                }
            }
        }
    }

    grid_barrier();

    // ================= phase 2: reduce split-K partials =================
    {
        const int base = bid * 194;                 // 148*194 = 28712 >= 28672
        const int k = base + tid;
        if (tid < 194 && k < NTOUT * 1024) {
            const float* p = g_scratch + k;
            float a0 = 0.f, a1 = 0.f, a2 = 0.f, a3 = 0.f;
            #pragma unroll 4
            for (int s = 0; s < GRID; s += 4) {
                a0 += p[(size_t)(s + 0) * (NTOUT * 1024)];
                a1 += p[(size_t)(s + 1) * (NTOUT * 1024)];
                a2 += p[(size_t)(s + 2) * (NTOUT * 1024)];
                a3 += p[(size_t)(s + 3) * (NTOUT * 1024)];
            }
            const float sum = (a0 + a1) + (a2 + a3);
            const int tl = k >> 10;
            const int r = (k >> 5) & 31;
            const int c = k & 31;
            const int gi = TIa[tl] * 32 + r;
            const int gj = TJa[tl] * 32 + c;
            if (gi < NR && gj < NR) g_inter[gi * NR + gj] = sum;
        }
    }

    grid_barrier();

    // ================= phase 3: matrix NMS math (CTA 0, exact jnp semantics) =================
    if (bid == 0) {
        float* sI = reinterpret_cast<float*>(smem);       // 200x200, overlays pipeline smem
        __shared__ float sums[NR];
        __shared__ float comp[NR];
        __shared__ int   lab[NR];
        __shared__ float sc[NR];

        for (int idx = tid; idx < NR * NR; idx += NTHREADS) sI[idx] = g_inter[idx];
        if (tid < NR) { lab[tid] = labels[tid]; sc[tid] = scores[tid]; }
        __syncthreads();
        if (tid < NR) sums[tid] = sI[tid * NR + tid];     // diag = mask area (binary)
        __syncthreads();

        if (tid < NR) {
            const int j = tid;
            const int lj = lab[j];
            const float sj = sums[j];
            float m = 0.f;
            for (int i = 0; i < j; i++) {
                if (lab[i] == lj) {
                    float in_ = sI[i * NR + j];
                    m = fmaxf(m, in_ / (sums[i] + sj - in_));
                }
            }
            comp[j] = m;
        }
        __syncthreads();

        if (tid < NR) {
            const int j = tid;
            const int lj = lab[j];
            const float sj = sums[j];
            float mn = 3.4e38f;
            for (int i = 0; i < NR; i++) {
                float d = 0.f;
                if (i < j && lab[i] == lj) {
                    float in_ = sI[i * NR + j];
                    d = in_ / (sums[i] + sj - in_);
                }
                float c = comp[i];
                mn = fminf(mn, c * c - d * d);
            }
            out[j] = sc[j] * expf(2.0f * mn);             // SIGMA = 2
        }
    }
}

// ============================ launch ============================
extern "C" void kernel_launch(void* const* d_in, const int* in_sizes, int n_in,
                              void* d_out, int out_size) {
    const float* seg    = (const float*)d_in[0];
    const float* scores = (const float*)d_in[1];
    const int*   labels = (const int*)d_in[2];
    float* out = (float*)d_out;

    cudaFuncSetAttribute(fused_kernel, cudaFuncAttributeMaxDynamicSharedMemorySize, DYN_SMEM);
    fused_kernel<<<GRID, NTHREADS, DYN_SMEM>>>(seg, scores, labels, out);
}

// round 4
// speedup vs baseline: 1.1180x; 1.1103x over previous
#include <cuda_runtime.h>
#include <cuda_bf16.h>
#include <cstdint>

// ============================ constants ============================
#define NR        200               // number of masks
#define HW        200704            // 448*448
#define NTK       3136              // total K tiles of 64
#define GRID      148
#define NTHREADS  512
#define ROWSTR    144               // bf16 buffer row stride in bytes (proven conflict-light)
#define STAGE_B   51200             // 200 rows * 64 fp32
#define BUF_B     (224*ROWSTR)      // 32256
#define OFF_BUF   (2*STAGE_B)
#define DYN_SMEM  (2*STAGE_B + 2*BUF_B)   // 166912
#define NTOUT     28                // upper-tri 32x32 output tiles (7x7 grid)
#define NPART     (NTOUT*1024)      // 28672 partial elements per split

__device__ float g_scratch[(size_t)GRID * NPART];   // ~17 MB
__device__ float g_inter[NR * NR];
__device__ unsigned g_count;
__device__ unsigned g_gen;

__device__ __constant__ unsigned char TIa[NTOUT] =
    {0,0,0,0,0,0,0, 1,1,1,1,1,1, 2,2,2,2,2, 3,3,3,3, 4,4,4, 5,5, 6};
__device__ __constant__ unsigned char TJa[NTOUT] =
    {0,1,2,3,4,5,6, 1,2,3,4,5,6, 2,3,4,5,6, 3,4,5,6, 4,5,6, 5,6, 6};

// ============================ helpers ============================
__device__ __forceinline__ uint32_t smem_u32(const void* p) {
    uint32_t a;
    asm("{ .reg .u64 t; cvta.to.shared.u64 t, %1; cvt.u32.u64 %0, t; }"
        : "=r"(a) : "l"(p));
    return a;
}

__device__ __forceinline__ void cp_async16(uint32_t sdst, const void* gsrc) {
    asm volatile("cp.async.cg.shared.global [%0], [%1], 16;"
                 :: "r"(sdst), "l"(gsrc) : "memory");
}
#define CP_COMMIT() asm volatile("cp.async.commit_group;" ::: "memory")
#define CP_WAIT0()  asm volatile("cp.async.wait_group 0;" ::: "memory")
#define CP_WAIT1()  asm volatile("cp.async.wait_group 1;" ::: "memory")

__device__ __forceinline__ void ldsm4(uint32_t* r, uint32_t addr) {
    asm volatile("ldmatrix.sync.aligned.m8n8.x4.shared.b16 {%0,%1,%2,%3}, [%4];"
                 : "=r"(r[0]), "=r"(r[1]), "=r"(r[2]), "=r"(r[3]) : "r"(addr));
}

__device__ __forceinline__ void mma16816(float* d, const uint32_t* a, const uint32_t* b) {
    asm volatile(
        "mma.sync.aligned.m16n8k16.row.col.f32.bf16.bf16.f32 "
        "{%0,%1,%2,%3}, {%4,%5,%6,%7}, {%8,%9}, {%0,%1,%2,%3};"
        : "+f"(d[0]), "+f"(d[1]), "+f"(d[2]), "+f"(d[3])
        : "r"(a[0]), "r"(a[1]), "r"(a[2]), "r"(a[3]), "r"(b[0]), "r"(b[1]));
}

// sense-reversal grid barrier; GRID CTAs co-resident (1 CTA/SM guaranteed by smem)
__device__ __forceinline__ void grid_barrier() {
    __syncthreads();
    if (threadIdx.x == 0) {
        __threadfence();
        unsigned gen = atomicAdd(&g_gen, 0u);
        unsigned arrived = atomicAdd(&g_count, 1u) + 1u;
        if (arrived == GRID) {
            atomicExch(&g_count, 0u);
            __threadfence();
            atomicAdd(&g_gen, 1u);
        } else {
            while (atomicAdd(&g_gen, 0u) == gen) { }
        }
        __threadfence();
    }
    __syncthreads();
}

__device__ __forceinline__ void issue_stage(uint32_t stage, const float* seg, int t, int tid) {
    const float* base = seg + (size_t)t * 64;
    #pragma unroll
    for (int it = 0; it < 6; it++) {
        int idx = tid + it * NTHREADS;
        int row = idx >> 4, c4 = idx & 15;
        cp_async16(stage + (uint32_t)idx * 16, base + (size_t)row * HW + c4 * 4);
    }
    if (tid < 128) {
        int idx = tid + 3072;
        int row = idx >> 4, c4 = idx & 15;
        cp_async16(stage + (uint32_t)idx * 16, base + (size_t)row * HW + c4 * 4);
    }
    CP_COMMIT();
}

__device__ __forceinline__ void convert_stage(char* smem, int stage_off, int buf_off, int tid) {
    #pragma unroll
    for (int it = 0; it < 7; it++) {
        int idx = tid + it * NTHREADS;
        if (idx < 3200) {
            int row = idx >> 4, c4 = idx & 15;
            float4 v = *reinterpret_cast<const float4*>(smem + stage_off + (size_t)idx * 16);
            __nv_bfloat162 p0 = __floats2bfloat162_rn(v.x, v.y);
            __nv_bfloat162 p1 = __floats2bfloat162_rn(v.z, v.w);
            uint2 w;
            w.x = *reinterpret_cast<uint32_t*>(&p0);
            w.y = *reinterpret_cast<uint32_t*>(&p1);
            *reinterpret_cast<uint2*>(smem + buf_off + (size_t)row * ROWSTR + c4 * 8) = w;
        }
    }
}

// ============================ fused kernel ============================
__global__ __launch_bounds__(NTHREADS, 1)
void fused_kernel(const float* __restrict__ seg,
                  const float* __restrict__ scores,
                  const int* __restrict__ labels,
                  float* __restrict__ out) {
    extern __shared__ char smem[];
    const uint32_t sbase = smem_u32(smem);
    const int tid = threadIdx.x;
    const int wid = tid >> 5;
    const int lid = tid & 31;
    const int bid = blockIdx.x;

    // ================= phase 1: split-K Gram (bf16 mma) =================
    {
        const int t0 = (bid * NTK) / GRID;
        const int t1 = ((bid + 1) * NTK) / GRID;

        // zero pad rows 200..223 of both bf16 buffers (written once)
        for (int i = tid; i < (24 * ROWSTR) / 4; i += NTHREADS) {
            *reinterpret_cast<uint32_t*>(smem + OFF_BUF + 200 * ROWSTR + i * 4) = 0u;
            *reinterpret_cast<uint32_t*>(smem + OFF_BUF + BUF_B + 200 * ROWSTR + i * 4) = 0u;
        }

        const int tl0 = wid;
        const int tl1 = wid + 16;
        const int nt = (tl1 < NTOUT) ? 2 : 1;
        int tis[2], tjs[2];
        tis[0] = TIa[tl0]; tjs[0] = TJa[tl0];
        tis[1] = TIa[(tl1 < NTOUT) ? tl1 : 0];
        tjs[1] = TJa[(tl1 < NTOUT) ? tl1 : 0];

        float acc[2][2][4][4];
        #pragma unroll
        for (int a = 0; a < 2; a++)
            #pragma unroll
            for (int b = 0; b < 2; b++)
                #pragma unroll
                for (int c = 0; c < 4; c++)
                    #pragma unroll
                    for (int d = 0; d < 4; d++) acc[a][b][c][d] = 0.f;

        const uint32_t aoff = (uint32_t)(lid & 15) * ROWSTR + (uint32_t)((lid >> 4) << 4);
        const uint32_t boff = (uint32_t)(((lid >> 4) << 3) + (lid & 7)) * ROWSTR
                            + (uint32_t)(((lid >> 3) & 1) << 4);

        // prologue
        issue_stage(sbase + (uint32_t)((t0 & 1) * STAGE_B), seg, t0, tid);
        if (t0 + 1 < t1) {
            issue_stage(sbase + (uint32_t)(((t0 + 1) & 1) * STAGE_B), seg, t0 + 1, tid);
            CP_WAIT1();
        } else {
            CP_WAIT0();
        }
        convert_stage(smem, (t0 & 1) * STAGE_B, OFF_BUF + (t0 & 1) * BUF_B, tid);
        __syncthreads();

        for (int t = t0; t < t1; t++) {
            const bool more1 = (t + 1 < t1);
            const bool more2 = (t + 2 < t1);
            if (more2)
                issue_stage(sbase + (uint32_t)((t & 1) * STAGE_B), seg, t + 2, tid);

            // compute tile t from buf[t&1] : 4 K-steps of K=16 bf16
            const uint32_t buf = sbase + OFF_BUF + (uint32_t)((t & 1) * BUF_B);
            #pragma unroll
            for (int ks = 0; ks < 4; ks++) {
                const uint32_t koff = (uint32_t)ks * 32;   // 16 bf16 = 32 bytes
                #pragma unroll
                for (int tt = 0; tt < 2; tt++) {
                    if (tt < nt) {
                        uint32_t afr[2][4], bfr[2][4];
                        uint32_t aA = buf + (uint32_t)(tis[tt] * 32) * ROWSTR + aoff + koff;
                        uint32_t aB = buf + (uint32_t)(tjs[tt] * 32) * ROWSTR + boff + koff;
                        ldsm4(afr[0], aA);
                        ldsm4(afr[1], aA + 16 * ROWSTR);
                        ldsm4(bfr[0], aB);
                        ldsm4(bfr[1], aB + 16 * ROWSTR);
                        #pragma unroll
                        for (int mh = 0; mh < 2; mh++)
                            #pragma unroll
                            for (int nq = 0; nq < 4; nq++)
                                mma16816(acc[tt][mh][nq], afr[mh], &bfr[nq >> 1][(nq & 1) * 2]);
                    }
                }
            }

            if (more1) {
                if (more2) { CP_WAIT1(); } else { CP_WAIT0(); }
                convert_stage(smem, ((t + 1) & 1) * STAGE_B,
                              OFF_BUF + ((t + 1) & 1) * BUF_B, tid);
                __syncthreads();
            }
        }

        // epilogue: fp32 partials -> scratch
        #pragma unroll
        for (int tt = 0; tt < 2; tt++) {
            if (tt < nt) {
                const int tl = (tt == 0) ? tl0 : tl1;
                float* dst = g_scratch + (size_t)bid * NPART + (size_t)tl * 1024;
                #pragma unroll
                for (int mh = 0; mh < 2; mh++) {
                    #pragma unroll
                    for (int nq = 0; nq < 4; nq++) {
                        const int r = mh * 16 + (lid >> 2);
                        const int c = nq * 8 + (lid & 3) * 2;
                        *reinterpret_cast<float2*>(dst + (size_t)r * 32 + c) =
                            make_float2(acc[tt][mh][nq][0], acc[tt][mh][nq][1]);
                        *reinterpret_cast<float2*>(dst + (size_t)(r + 8) * 32 + c) =
                            make_float2(acc[tt][mh][nq][2], acc[tt][mh][nq][3]);
                    }
                }
            }
        }
    }

    grid_barrier();

    // ================= phase 2: reduce split-K partials =================
    // 112 CTAs x 8 jobs x 2 warps/job. Job = 32 consecutive elements; each
    // warp sums 74 of the 148 slabs (coalesced 128B lines), pair-combine in smem.
    {
        float* sred = reinterpret_cast<float*>(smem);     // 256 floats
        if (bid < 112) {
            const int job = (bid << 3) + (wid >> 1);      // 0..895
            const int e = (job << 5) + lid;               // element index
            const int s0 = (wid & 1) * 74;
            const float* p = g_scratch + (size_t)s0 * NPART + e;
            float a = 0.f, b = 0.f;
            #pragma unroll
            for (int k = 0; k < 74; k += 2) {
                a += p[(size_t)k * NPART];
                b += p[(size_t)(k + 1) * NPART];
            }
            const float part = a + b;
            if (wid & 1) sred[((wid >> 1) << 5) + lid] = part;
            __syncthreads();
            if (!(wid & 1)) {
                const float sum = part + sred[((wid >> 1) << 5) + lid];
                const int tl = e >> 10;
                const int r = (e >> 5) & 31;
                const int c = e & 31;
                const int gi = TIa[tl] * 32 + r;
                const int gj = TJa[tl] * 32 + c;
                if (gi < NR && gj < NR) g_inter[gi * NR + gj] = sum;
            }
        }
    }

    grid_barrier();

    // ================= phase 3: matrix NMS math (CTA 0, exact jnp semantics) =================
    if (bid == 0) {
        __shared__ float sums[NR];
        __shared__ float comp[NR];
        __shared__ int   lab[NR];
        __shared__ float sc[NR];

        if (tid < NR) {
            lab[tid] = labels[tid];
            sc[tid] = scores[tid];
            sums[tid] = g_inter[tid * NR + tid];          // diag = mask area
        }
        __syncthreads();

        if (tid < NR) {
            const int j = tid;
            const int lj = lab[j];
            const float sj = sums[j];
            float m = 0.f;
            for (int i = 0; i < j; i++) {
                if (lab[i] == lj) {
                    float in_ = __ldg(&g_inter[i * NR + j]);   // L2-hot
                    m = fmaxf(m, in_ / (sums[i] + sj - in_));
                }
            }
            comp[j] = m;
        }
        __syncthreads();

        if (tid < NR) {
            const int j = tid;
            const int lj = lab[j];
            const float sj = sums[j];
            float mn = 3.4e38f;
            for (int i = 0; i < NR; i++) {
                float d = 0.f;
                if (i < j && lab[i] == lj) {
                    float in_ = __ldg(&g_inter[i * NR + j]);
                    d = in_ / (sums[i] + sj - in_);
                }
                float c = comp[i];
                mn = fminf(mn, c * c - d * d);
            }
            out[j] = sc[j] * expf(2.0f * mn);             // SIGMA = 2
        }
    }
}

// ============================ launch ============================
extern "C" void kernel_launch(void* const* d_in, const int* in_sizes, int n_in,
                              void* d_out, int out_size) {
    const float* seg    = (const float*)d_in[0];
    const float* scores = (const float*)d_in[1];
    const int*   labels = (const int*)d_in[2];
    float* out = (float*)d_out;

    cudaFuncSetAttribute(fused_kernel, cudaFuncAttributeMaxDynamicSharedMemorySize, DYN_SMEM);
    fused_kernel<<<GRID, NTHREADS, DYN_SMEM>>>(seg, scores, labels, out);
}

// round 5
// speedup vs baseline: 1.7310x; 1.5483x over previous
#include <cuda_runtime.h>
#include <cuda_bf16.h>
#include <cstdint>

// ============================ constants ============================
#define NR        200               // number of masks
#define HW        200704            // 448*448
#define NTK       3136              // total K tiles of 64
#define GRID      148
#define NTHREADS  512
#define ROWSTR    144               // bf16 buffer row stride in bytes
#define STAGE_B   51200             // 200 rows * 64 fp32
#define BUF_B     (224*ROWSTR)      // 32256
#define OFF_BUF   (2*STAGE_B)
#define DYN_SMEM  (2*STAGE_B + 2*BUF_B)   // 166912
#define NTOUT     28                // upper-tri 32x32 tiles (7x7 grid)
#define NPART     (49*1024)         // scratch slab: full 7x7 tile grid, 50176 floats

__device__ float g_scratch[(size_t)GRID * NPART];   // ~29.7 MB
__device__ float g_inter[NR * NR];
__device__ float g_comp[256];
__device__ unsigned g_count;
__device__ unsigned g_gen;

// upper-tri linear tile -> (ti, tj)
__device__ __constant__ unsigned char TIa[NTOUT] =
    {0,0,0,0,0,0,0, 1,1,1,1,1,1, 2,2,2,2,2, 3,3,3,3, 4,4,4, 5,5, 6};
__device__ __constant__ unsigned char TJa[NTOUT] =
    {0,1,2,3,4,5,6, 1,2,3,4,5,6, 2,3,4,5,6, 3,4,5,6, 4,5,6, 5,6, 6};

// per-warp gram jobs: 12 pairs (A-fragment shared across 2 tj) + 4 singles = 16
__device__ __constant__ unsigned char JTI[16] = {0,0,0, 1,1,1, 2,2, 3,3, 4, 5, 0, 2, 4, 6};
__device__ __constant__ unsigned char JT0[16] = {0,2,4, 1,3,5, 2,4, 3,5, 4, 5, 6, 6, 6, 6};
__device__ __constant__ unsigned char JN [16] = {2,2,2, 2,2,2, 2,2, 2,2, 2, 2, 1, 1, 1, 1};

// ============================ helpers ============================
__device__ __forceinline__ uint32_t smem_u32(const void* p) {
    uint32_t a;
    asm("{ .reg .u64 t; cvta.to.shared.u64 t, %1; cvt.u32.u64 %0, t; }"
        : "=r"(a) : "l"(p));
    return a;
}

__device__ __forceinline__ void cp_async16(uint32_t sdst, const void* gsrc) {
    asm volatile("cp.async.cg.shared.global [%0], [%1], 16;"
                 :: "r"(sdst), "l"(gsrc) : "memory");
}
#define CP_COMMIT() asm volatile("cp.async.commit_group;" ::: "memory")
#define CP_WAIT0()  asm volatile("cp.async.wait_group 0;" ::: "memory")
#define CP_WAIT1()  asm volatile("cp.async.wait_group 1;" ::: "memory")

__device__ __forceinline__ void ldsm4(uint32_t* r, uint32_t addr) {
    asm volatile("ldmatrix.sync.aligned.m8n8.x4.shared.b16 {%0,%1,%2,%3}, [%4];"
                 : "=r"(r[0]), "=r"(r[1]), "=r"(r[2]), "=r"(r[3]) : "r"(addr));
}

__device__ __forceinline__ void mma16816(float* d, const uint32_t* a, const uint32_t* b) {
    asm volatile(
        "mma.sync.aligned.m16n8k16.row.col.f32.bf16.bf16.f32 "
        "{%0,%1,%2,%3}, {%4,%5,%6,%7}, {%8,%9}, {%0,%1,%2,%3};"
        : "+f"(d[0]), "+f"(d[1]), "+f"(d[2]), "+f"(d[3])
        : "r"(a[0]), "r"(a[1]), "r"(a[2]), "r"(a[3]), "r"(b[0]), "r"(b[1]));
}

// grid barrier: atomic arrivals, PLAIN-LOAD polling with nanosleep backoff
// (atomic spin storms serialize the L2 atomic ALU and stall the release)
__device__ __forceinline__ void grid_barrier() {
    __syncthreads();
    if (threadIdx.x == 0) {
        __threadfence();
        unsigned gen = *(volatile unsigned*)&g_gen;       // snapshot BEFORE arriving
        unsigned arrived = atomicAdd(&g_count, 1u) + 1u;
        if (arrived == GRID) {
            atomicExch(&g_count, 0u);
            __threadfence();
            atomicAdd(&g_gen, 1u);                        // release
        } else {
            while (*(volatile unsigned*)&g_gen == gen) __nanosleep(128);
        }
        __threadfence();
    }
    __syncthreads();
}

__device__ __forceinline__ void issue_stage(uint32_t stage, const float* seg, int t, int tid) {
    const float* base = seg + (size_t)t * 64;
    #pragma unroll
    for (int it = 0; it < 6; it++) {
        int idx = tid + it * NTHREADS;
        int row = idx >> 4, c4 = idx & 15;
        cp_async16(stage + (uint32_t)idx * 16, base + (size_t)row * HW + c4 * 4);
    }
    if (tid < 128) {
        int idx = tid + 3072;
        int row = idx >> 4, c4 = idx & 15;
        cp_async16(stage + (uint32_t)idx * 16, base + (size_t)row * HW + c4 * 4);
    }
    CP_COMMIT();
}

__device__ __forceinline__ void convert_stage(char* smem, int stage_off, int buf_off, int tid) {
    #pragma unroll
    for (int it = 0; it < 7; it++) {
        int idx = tid + it * NTHREADS;
        if (idx < 3200) {
            int row = idx >> 4, c4 = idx & 15;
            float4 v = *reinterpret_cast<const float4*>(smem + stage_off + (size_t)idx * 16);
            __nv_bfloat162 p0 = __floats2bfloat162_rn(v.x, v.y);
            __nv_bfloat162 p1 = __floats2bfloat162_rn(v.z, v.w);
            uint2 w;
            w.x = *reinterpret_cast<uint32_t*>(&p0);
            w.y = *reinterpret_cast<uint32_t*>(&p1);
            *reinterpret_cast<uint2*>(smem + buf_off + (size_t)row * ROWSTR + c4 * 8) = w;
        }
    }
}

// ============================ fused kernel ============================
__global__ __launch_bounds__(NTHREADS, 1)
void fused_kernel(const float* __restrict__ seg,
                  const float* __restrict__ scores,
                  const int* __restrict__ labels,
                  float* __restrict__ out) {
    extern __shared__ char smem[];
    const uint32_t sbase = smem_u32(smem);
    const int tid = threadIdx.x;
    const int wid = tid >> 5;
    const int lid = tid & 31;
    const int bid = blockIdx.x;

    // ================= phase 1: split-K Gram (bf16 mma, A-fragment reuse) =================
    {
        const int t0 = (bid * NTK) / GRID;
        const int t1 = ((bid + 1) * NTK) / GRID;

        // zero pad rows 200..223 of both bf16 buffers (written once)
        for (int i = tid; i < (24 * ROWSTR) / 4; i += NTHREADS) {
            *reinterpret_cast<uint32_t*>(smem + OFF_BUF + 200 * ROWSTR + i * 4) = 0u;
            *reinterpret_cast<uint32_t*>(smem + OFF_BUF + BUF_B + 200 * ROWSTR + i * 4) = 0u;
        }

        const int ti  = JTI[wid];
        const int tj0 = JT0[wid];
        const int njt = JN[wid];

        float acc[2][2][4][4];
        #pragma unroll
        for (int a = 0; a < 2; a++)
            #pragma unroll
            for (int b = 0; b < 2; b++)
                #pragma unroll
                for (int c = 0; c < 4; c++)
                    #pragma unroll
                    for (int d = 0; d < 4; d++) acc[a][b][c][d] = 0.f;

        const uint32_t aoff = (uint32_t)(lid & 15) * ROWSTR + (uint32_t)((lid >> 4) << 4);
        const uint32_t boff = (uint32_t)(((lid >> 4) << 3) + (lid & 7)) * ROWSTR
                            + (uint32_t)(((lid >> 3) & 1) << 4);

        // prologue
        issue_stage(sbase + (uint32_t)((t0 & 1) * STAGE_B), seg, t0, tid);
        if (t0 + 1 < t1) {
            issue_stage(sbase + (uint32_t)(((t0 + 1) & 1) * STAGE_B), seg, t0 + 1, tid);
            CP_WAIT1();
        } else {
            CP_WAIT0();
        }
        convert_stage(smem, (t0 & 1) * STAGE_B, OFF_BUF + (t0 & 1) * BUF_B, tid);
        __syncthreads();

        for (int t = t0; t < t1; t++) {
            const bool more1 = (t + 1 < t1);
            const bool more2 = (t + 2 < t1);
            if (more2)
                issue_stage(sbase + (uint32_t)((t & 1) * STAGE_B), seg, t + 2, tid);

            const uint32_t buf = sbase + OFF_BUF + (uint32_t)((t & 1) * BUF_B);
            #pragma unroll
            for (int ks = 0; ks < 4; ks++) {
                const uint32_t koff = (uint32_t)ks * 32;   // 16 bf16 = 32 bytes
                uint32_t afr[2][4];
                const uint32_t aA = buf + (uint32_t)(ti * 32) * ROWSTR + aoff + koff;
                ldsm4(afr[0], aA);
                ldsm4(afr[1], aA + 16 * ROWSTR);
                #pragma unroll
                for (int nn = 0; nn < 2; nn++) {
                    if (nn < njt) {
                        uint32_t bfr[2][4];
                        const uint32_t aB = buf + (uint32_t)((tj0 + nn) * 32) * ROWSTR + boff + koff;
                        ldsm4(bfr[0], aB);
                        ldsm4(bfr[1], aB + 16 * ROWSTR);
                        #pragma unroll
                        for (int mh = 0; mh < 2; mh++)
                            #pragma unroll
                            for (int nq = 0; nq < 4; nq++)
                                mma16816(acc[nn][mh][nq], afr[mh], &bfr[nq >> 1][(nq & 1) * 2]);
                    }
                }
            }

            if (more1) {
                if (more2) { CP_WAIT1(); } else { CP_WAIT0(); }
                convert_stage(smem, ((t + 1) & 1) * STAGE_B,
                              OFF_BUF + ((t + 1) & 1) * BUF_B, tid);
                __syncthreads();
            }
        }

        // epilogue: fp32 partials -> scratch (slab indexed by (ti,tj) in 7x7 grid)
        #pragma unroll
        for (int nn = 0; nn < 2; nn++) {
            if (nn < njt) {
                float* dst = g_scratch + (size_t)bid * NPART
                           + (size_t)(ti * 7 + (tj0 + nn)) * 1024;
                #pragma unroll
                for (int mh = 0; mh < 2; mh++) {
                    #pragma unroll
                    for (int nq = 0; nq < 4; nq++) {
                        const int r = mh * 16 + (lid >> 2);
                        const int c = nq * 8 + (lid & 3) * 2;
                        *reinterpret_cast<float2*>(dst + (size_t)r * 32 + c) =
                            make_float2(acc[nn][mh][nq][0], acc[nn][mh][nq][1]);
                        *reinterpret_cast<float2*>(dst + (size_t)(r + 8) * 32 + c) =
                            make_float2(acc[nn][mh][nq][2], acc[nn][mh][nq][3]);
                    }
                }
            }
        }
    }

    grid_barrier();

    // ================= phase 2: reduce split-K partials (all 148 CTAs) =================
    // 896 jobs of 32 elements; 2 warps per job, 74 slabs each, smem pair-combine.
    {
        float* sred = reinterpret_cast<float*>(smem);     // 256 floats
        const int gw = bid * 16 + wid;
        const int job = gw >> 1;
        const bool active = job < 896;
        float part = 0.f;
        int e = 0, off = 0;
        if (active) {
            e = (job << 5) + lid;
            const int tl = e >> 10;
            off = ((int)TIa[tl] * 7 + (int)TJa[tl]) * 1024 + (e & 1023);
            const float* p = g_scratch + (size_t)((gw & 1) * 74) * NPART + off;
            float a = 0.f, b = 0.f;
            #pragma unroll
            for (int k = 0; k < 74; k += 2) {
                a += p[(size_t)k * NPART];
                b += p[(size_t)(k + 1) * NPART];
            }
            part = a + b;
        }
        if (active && (gw & 1)) sred[((wid >> 1) << 5) + lid] = part;
        __syncthreads();
        if (active && !(gw & 1)) {
            const float sum = part + sred[((wid >> 1) << 5) + lid];
            const int tl = e >> 10;
            const int gi = TIa[tl] * 32 + ((e >> 5) & 31);
            const int gj = TJa[tl] * 32 + (e & 31);
            if (gi < NR && gj < NR) g_inter[gi * NR + gj] = sum;
        }
    }

    grid_barrier();

    // ================= phase 3a: compensate IoU, one warp per j =================
    {
        const int j = bid * 16 + wid;
        if (j < NR) {
            const int lj = labels[j];
            const float sj = g_inter[j * NR + j];
            float m = 0.f;
            for (int i = lid; i < j; i += 32) {
                if (labels[i] == lj) {
                    const float in_ = g_inter[i * NR + j];
                    m = fmaxf(m, in_ / (g_inter[i * NR + i] + sj - in_));
                }
            }
            #pragma unroll
            for (int o = 16; o; o >>= 1) m = fmaxf(m, __shfl_xor_sync(~0u, m, o));
            if (lid == 0) g_comp[j] = m;
        }
    }

    grid_barrier();

    // ================= phase 3b: decay coefficient (min over ALL i), one warp per j =================
    {
        const int j = bid * 16 + wid;
        if (j < NR) {
            const int lj = labels[j];
            const float sj = g_inter[j * NR + j];
            float mn = 3.4e38f;
            for (int i = lid; i < NR; i += 32) {
                float d = 0.f;
                if (i < j && labels[i] == lj) {
                    const float in_ = g_inter[i * NR + j];
                    d = in_ / (g_inter[i * NR + i] + sj - in_);
                }
                const float c = g_comp[i];
                mn = fminf(mn, c * c - d * d);
            }
            #pragma unroll
            for (int o = 16; o; o >>= 1) mn = fminf(mn, __shfl_xor_sync(~0u, mn, o));
            if (lid == 0) out[j] = scores[j] * expf(2.0f * mn);   // SIGMA = 2
        }
    }
}

// ============================ launch ============================
extern "C" void kernel_launch(void* const* d_in, const int* in_sizes, int n_in,
                              void* d_out, int out_size) {
    const float* seg    = (const float*)d_in[0];
    const float* scores = (const float*)d_in[1];
    const int*   labels = (const int*)d_in[2];
    float* out = (float*)d_out;

    cudaFuncSetAttribute(fused_kernel, cudaFuncAttributeMaxDynamicSharedMemorySize, DYN_SMEM);
    fused_kernel<<<GRID, NTHREADS, DYN_SMEM>>>(seg, scores, labels, out);
}